// round 9
// baseline (speedup 1.0000x reference)
#include <cuda_runtime.h>
#include <float.h>

// Scratch accumulators — zero-initialized at module load, and re-zeroed by
// finalize_kernel at the end of every invocation (so each graph replay starts
// clean). Sized for B=4096, H=128.
__device__ float        g_sum[4096 * 128];     // segment sums
__device__ unsigned int g_maxk[4096 * 128];    // order-preserving max keys; 0 == -inf
__device__ int          g_counts[4096];        // segment element counts

// Order-preserving float<->uint key. Monotone: f1 < f2 <=> key(f1) < key(f2).
// key(x) >= 1 for all finite x, so a zero key acts as -infinity.
__device__ __forceinline__ unsigned int fkey(float f) {
    unsigned int b = __float_as_uint(f);
    return (b & 0x80000000u) ? ~b : (b | 0x80000000u);
}
__device__ __forceinline__ float funkey(unsigned int k) {
    return __uint_as_float((k & 0x80000000u) ? (k & 0x7FFFFFFFu) : ~k);
}

struct Acc {
    float4 s, m;
    int cnt, cur;
};

__device__ __forceinline__ void flush_acc(const Acc& a, int lane, int B) {
    int cc = min(max(a.cur, 0), B - 1);
    float* sb = g_sum + cc * 128 + lane * 4;
    atomicAdd(sb + 0, a.s.x);
    atomicAdd(sb + 1, a.s.y);
    atomicAdd(sb + 2, a.s.z);
    atomicAdd(sb + 3, a.s.w);
    unsigned int* mb = g_maxk + cc * 128 + lane * 4;
    atomicMax(mb + 0, fkey(a.m.x));
    atomicMax(mb + 1, fkey(a.m.y));
    atomicMax(mb + 2, fkey(a.m.z));
    atomicMax(mb + 3, fkey(a.m.w));
    if (lane == 0) atomicAdd(&g_counts[cc], a.cnt);
}

__device__ __forceinline__ void step_acc(Acc& a, int b, float4 v,
                                         int lane, int B) {
    if (b != a.cur) {
        flush_acc(a, lane, B);
        a.s = make_float4(0.f, 0.f, 0.f, 0.f);
        a.m = make_float4(-FLT_MAX, -FLT_MAX, -FLT_MAX, -FLT_MAX);
        a.cnt = 0;
        a.cur = b;
    }
    a.s.x += v.x; a.s.y += v.y; a.s.z += v.z; a.s.w += v.w;
    a.m.x = fmaxf(a.m.x, v.x);
    a.m.y = fmaxf(a.m.y, v.y);
    a.m.z = fmaxf(a.m.z, v.z);
    a.m.w = fmaxf(a.m.w, v.w);
    a.cnt++;
}

// One warp per contiguous row range (4-row aligned). Lanes each own a float4
// (4 features) of the 128-wide row. Rows processed in chunks of 4 with all
// loads issued up-front (batch ids via one int4 load, x via 4 streaming
// float4 loads) to hide the ~577-cyc DRAM latency. Accumulate sum/max/count
// in registers; flush to scratch atomically on segment change.
__global__ void __launch_bounds__(256) agg_kernel(
    const float4* __restrict__ x,       // [N, 32] float4 view of [N, 128]
    const int* __restrict__ batch,      // [N] sorted segment ids (int32)
    int N, int B)
{
    int gtid   = blockIdx.x * blockDim.x + threadIdx.x;
    int warp   = gtid >> 5;
    int lane   = gtid & 31;
    int nwarps = (gridDim.x * blockDim.x) >> 5;

    // 4-row-aligned contiguous ranges (keeps int4 batch loads aligned).
    long long start = (((long long)N * warp / nwarps) + 3) & ~3LL;
    long long end   = (((long long)N * (warp + 1) / nwarps) + 3) & ~3LL;
    if (end > N) end = N;
    if (start >= end) return;

    Acc a;
    a.s = make_float4(0.f, 0.f, 0.f, 0.f);
    a.m = make_float4(-FLT_MAX, -FLT_MAX, -FLT_MAX, -FLT_MAX);
    a.cnt = 0;
    a.cur = __ldcs(&batch[start]);

    long long r = start;
    // Unrolled-by-4 main loop: batch all loads, then process.
    for (; r + 4 <= end; r += 4) {
        int4 b4 = __ldcs((const int4*)&batch[r]);
        float4 v0 = __ldcs(&x[(r + 0) * 32 + lane]);
        float4 v1 = __ldcs(&x[(r + 1) * 32 + lane]);
        float4 v2 = __ldcs(&x[(r + 2) * 32 + lane]);
        float4 v3 = __ldcs(&x[(r + 3) * 32 + lane]);
        step_acc(a, b4.x, v0, lane, B);
        step_acc(a, b4.y, v1, lane, B);
        step_acc(a, b4.z, v2, lane, B);
        step_acc(a, b4.w, v3, lane, B);
    }
    // Remainder (< 4 rows, only at the very end of the array).
    for (; r < end; ++r) {
        int b = __ldcs(&batch[r]);
        float4 v = __ldcs(&x[r * 32 + lane]);
        step_acc(a, b, v, lane, B);
    }

    flush_acc(a, lane, B);
}

// Vectorized finalize: one thread per (segment, float4 feature group).
// Reads scratch as 16B vectors, writes out [sum | mean | max] with streaming
// stores, then resets scratch to zero for the next invocation. Each segment's
// 32 threads live in one 256-thread block (8 segments/block), so the count
// read/reset pair is ordered with __syncthreads().
__global__ void __launch_bounds__(256) finalize_kernel(float* __restrict__ out, int B) {
    int i = blockIdx.x * blockDim.x + threadIdx.x;   // 0 .. B*32-1
    if (i >= B * 32) return;
    int b  = i >> 5;        // segment
    int h4 = i & 31;        // float4 group within 128 features

    float4 s = ((const float4*)g_sum)[i];
    uint4  k = ((const uint4*)g_maxk)[i];
    int    c = g_counts[b];
    __syncthreads();        // all reads of g_counts[b] before reset

    float inv = 1.0f / fmaxf((float)c, 1.0f);
    float4 mean = make_float4(s.x * inv, s.y * inv, s.z * inv, s.w * inv);
    float4 mx;
    if (c > 0) {
        mx = make_float4(funkey(k.x), funkey(k.y), funkey(k.z), funkey(k.w));
    } else {
        mx = make_float4(0.f, 0.f, 0.f, 0.f);
    }

    float4* row = (float4*)(out + (long long)b * 384);
    __stcs(row + h4,      s);
    __stcs(row + 32 + h4, mean);
    __stcs(row + 64 + h4, mx);

    // Reset scratch for next run.
    ((float4*)g_sum)[i] = make_float4(0.f, 0.f, 0.f, 0.f);
    ((uint4*)g_maxk)[i] = make_uint4(0u, 0u, 0u, 0u);
    if (h4 == 0) g_counts[b] = 0;
}

extern "C" void kernel_launch(void* const* d_in, const int* in_sizes, int n_in,
                              void* d_out, int out_size) {
    const float4* x  = (const float4*)d_in[0];
    const int* batch = (const int*)d_in[1];   // int32 on device (verified)
    float* out       = (float*)d_out;

    int N = in_sizes[1];           // number of rows
    int B = out_size / 384;        // segments (out is [B, 3*128])

    // Main aggregation: 1216 blocks (8 CTAs x 152 SMs) x 256 threads.
    {
        int threads = 256;
        int blocks  = 1216;
        agg_kernel<<<blocks, threads>>>(x, batch, N, B);
    }

    // Finalize: write out + reset scratch (one thread per 4 features).
    {
        int threads = 256;
        int blocks  = (B * 32 + threads - 1) / threads;
        finalize_kernel<<<blocks, threads>>>(out, B);
    }
}